// round 7
// baseline (speedup 1.0000x reference)
#include <cuda_runtime.h>
#include <cuda_bf16.h>
#include <mma.h>
#include <math.h>
#include <stdint.h>

using namespace nvcuda;

#define BN_EPS 1e-5f

// ============================ scratch (device globals) ============================
__device__ __nv_bfloat16 g_s_hi[10240 * 4096], g_s_lo[10240 * 4096];
__device__ __nv_bfloat16 g_f_hi[10240 * 1024], g_f_lo[10240 * 1024];
__device__ __nv_bfloat16 g_b_hi[1024 * 2048],  g_b_lo[1024 * 2048];
__device__ __nv_bfloat16 g_w1s_hi[512 * 4096], g_w1s_lo[512 * 4096];
__device__ __nv_bfloat16 g_w2s_hi[128 * 512],  g_w2s_lo[128 * 512];
__device__ __nv_bfloat16 g_w1o_hi[128 * 1024], g_w1o_lo[128 * 1024];
__device__ __nv_bfloat16 g_w2o_hi[128 * 128],  g_w2o_lo[128 * 128];
__device__ __nv_bfloat16 g_w1b_hi[256 * 2048], g_w1b_lo[256 * 2048];
__device__ __nv_bfloat16 g_w2b_hi[128 * 256],  g_w2b_lo[128 * 256];
__device__ __nv_bfloat16 g_hs_hi[10240 * 512], g_hs_lo[10240 * 512];
__device__ __nv_bfloat16 g_ho_hi[10240 * 128], g_ho_lo[10240 * 128];
__device__ __nv_bfloat16 g_hb_hi[1024 * 256],  g_hb_lo[1024 * 256];
__device__ float g_obj[10240 * 128];
__device__ float g_sen[10240 * 128];
__device__ float g_bod[1024 * 128];
__device__ float g_xs[1024 * 688];
__device__ float g_bns_s[512], g_bns_t[512];
__device__ float g_bno_s[128], g_bno_t[128];
__device__ float g_bnb_s[256], g_bnb_t[256];
__device__ float g_bnf_s[256], g_bnf_t[256];

// ============================ helpers ============================
__device__ __forceinline__ uint32_t smem_u32(const void* p) {
    uint32_t a;
    asm("{ .reg .u64 t; cvta.to.shared.u64 t, %1; cvt.u32.u64 %0, t; }" : "=r"(a) : "l"(p));
    return a;
}
__device__ __forceinline__ void cp_async16(uint32_t saddr, const void* gptr) {
    asm volatile("cp.async.cg.shared.global [%0], [%1], 16;" :: "r"(saddr), "l"(gptr));
}
__device__ __forceinline__ void cp_commit() {
    asm volatile("cp.async.commit_group;" ::: "memory");
}
template<int N>
__device__ __forceinline__ void cp_wait() {
    asm volatile("cp.async.wait_group %0;" :: "n"(N) : "memory");
}

// ============================ BN fold prep ============================
__global__ void prep_bn_kernel(
    const float* __restrict__ gs, const float* __restrict__ bs,
    const float* __restrict__ ms, const float* __restrict__ vs,
    const float* __restrict__ go, const float* __restrict__ bo,
    const float* __restrict__ mo, const float* __restrict__ vo,
    const float* __restrict__ gb, const float* __restrict__ bb,
    const float* __restrict__ mb, const float* __restrict__ vb,
    const float* __restrict__ gf, const float* __restrict__ bfv,
    const float* __restrict__ mf, const float* __restrict__ vf,
    const float* __restrict__ bias_f)
{
    int i = threadIdx.x;
    if (i < 512) { float s = gs[i] * rsqrtf(vs[i] + BN_EPS); g_bns_s[i] = s; g_bns_t[i] = bs[i] - ms[i] * s; }
    if (i < 128) { float s = go[i] * rsqrtf(vo[i] + BN_EPS); g_bno_s[i] = s; g_bno_t[i] = bo[i] - mo[i] * s; }
    if (i < 256) { float s = gb[i] * rsqrtf(vb[i] + BN_EPS); g_bnb_s[i] = s; g_bnb_t[i] = bb[i] - mb[i] * s; }
    if (i < 256) { float s = gf[i] * rsqrtf(vf[i] + BN_EPS); g_bnf_s[i] = s; g_bnf_t[i] = (bias_f[i] - mf[i]) * s + bfv[i]; }
}

// ============================ fp32 -> bf16 hi/lo split (MLP=4) ============================
__global__ void split_kernel(const float4* __restrict__ src,
                             uint2* __restrict__ hi, uint2* __restrict__ lo, int n4)
{
    const int base = blockIdx.x * (blockDim.x * 4) + threadIdx.x;
    float4 v[4];
    int idx[4];
    bool ok[4];
#pragma unroll
    for (int j = 0; j < 4; j++) {
        idx[j] = base + j * blockDim.x;
        ok[j] = idx[j] < n4;
        if (ok[j]) v[j] = src[idx[j]];
    }
#pragma unroll
    for (int j = 0; j < 4; j++) {
        if (!ok[j]) continue;
        union { __nv_bfloat16 h[4]; uint2 u; } H, L;
        H.h[0] = __float2bfloat16(v[j].x); L.h[0] = __float2bfloat16(v[j].x - __bfloat162float(H.h[0]));
        H.h[1] = __float2bfloat16(v[j].y); L.h[1] = __float2bfloat16(v[j].y - __bfloat162float(H.h[1]));
        H.h[2] = __float2bfloat16(v[j].z); L.h[2] = __float2bfloat16(v[j].z - __bfloat162float(H.h[2]));
        H.h[3] = __float2bfloat16(v[j].w); L.h[3] = __float2bfloat16(v[j].w - __bfloat162float(H.h[3]));
        hi[idx[j]] = H.u; lo[idx[j]] = L.u;
    }
}

// ============================ wmma bf16x3 GEMM v2 ============================
// C[M,N_TOT] = (Ahi+Alo)[M,K] @ (Bhi+Blo)[N_TOT,K]^T  (3-term split, fp32 accum)
// Block tile 128x128, BK=64, 2-stage cp.async pipeline.
// 256 threads, 8 warps as 4x2, warp tile 32x64 (2x4 fragments).
// grid = (N_TOT/128, M/128).
template<int K, bool BN_RELU>
__global__ __launch_bounds__(256)
void wmma_gemm(int N_TOT,
    const __nv_bfloat16* __restrict__ Ahi, const __nv_bfloat16* __restrict__ Alo,
    const __nv_bfloat16* __restrict__ Bhi, const __nv_bfloat16* __restrict__ Blo,
    float* __restrict__ Cf,
    __nv_bfloat16* __restrict__ Chi, __nv_bfloat16* __restrict__ Clo,
    const float* __restrict__ sc, const float* __restrict__ sh)
{
    constexpr int BK = 64;
    constexpr int KITERS = K / BK;
    constexpr int TOTAL = 3 * KITERS;
    constexpr int LDT = 72;                 // 144B row stride: 16B multiple, conflict-staggered
    constexpr int A_STG = 128 * LDT * 2;    // 18432 B
    constexpr int B_STG = 128 * LDT * 2;    // 18432 B
    // A0 | A1 | B0 | B1 = 73728 B; epilogue scratch (8 warps * 32x68 f32 = 69632 B) unions at 0
    extern __shared__ __align__(16) char smraw[];
    const uint32_t sbase = smem_u32(smraw);

    const int tid = threadIdx.x;
    const int wid = tid >> 5;
    const int lane = tid & 31;
    const int warp_m = wid & 3;   // 4 slabs of 32 rows
    const int warp_n = wid >> 2;  // 2 slabs of 64 cols
    const int bm0 = blockIdx.y * 128;
    const int bn0 = blockIdx.x * 128;

    wmma::fragment<wmma::accumulator, 16, 16, 16, float> c[2][4];
#pragma unroll
    for (int mi = 0; mi < 2; mi++)
#pragma unroll
        for (int ni = 0; ni < 4; ni++) wmma::fill_fragment(c[mi][ni], 0.0f);

    const int lr = tid >> 3;      // 0..31
    const int lq = tid & 7;       // 16B segment in 64-bf16 row chunk

    auto load_stage = [&](int it, int stage) {
        const int t = it / KITERS, cix = it % KITERS;
        const __nv_bfloat16* Ap = (t == 1) ? Alo : Ahi;
        const __nv_bfloat16* Bp = (t == 2) ? Blo : Bhi;
        const uint32_t abase = sbase + stage * A_STG;
        const uint32_t bbase = sbase + 2 * A_STG + stage * B_STG;
#pragma unroll
        for (int i = 0; i < 4; i++) {   // A: 128 rows x 64 bf16
            int r = lr + i * 32;
            cp_async16(abase + r * (LDT * 2) + lq * 16,
                       Ap + (size_t)(bm0 + r) * K + cix * 64 + lq * 8);
        }
#pragma unroll
        for (int i = 0; i < 4; i++) {   // B: 128 rows x 64 bf16
            int r = lr + i * 32;
            cp_async16(bbase + r * (LDT * 2) + lq * 16,
                       Bp + (size_t)(bn0 + r) * K + cix * 64 + lq * 8);
        }
        cp_commit();
    };

    __nv_bfloat16* As = reinterpret_cast<__nv_bfloat16*>(smraw);
    __nv_bfloat16* Bs = reinterpret_cast<__nv_bfloat16*>(smraw + 2 * A_STG);

    load_stage(0, 0);
    for (int it = 0; it < TOTAL; ++it) {
        const int stage = it & 1;
        if (it + 1 < TOTAL) {
            load_stage(it + 1, stage ^ 1);
            cp_wait<1>();
        } else {
            cp_wait<0>();
        }
        __syncthreads();

        const __nv_bfloat16* Ast = As + stage * (128 * LDT);
        const __nv_bfloat16* Bst = Bs + stage * (128 * LDT);
#pragma unroll
        for (int kk = 0; kk < 4; kk++) {
            wmma::fragment<wmma::matrix_a, 16, 16, 16, __nv_bfloat16, wmma::row_major> a[2];
            wmma::fragment<wmma::matrix_b, 16, 16, 16, __nv_bfloat16, wmma::col_major> b[4];
#pragma unroll
            for (int mi = 0; mi < 2; mi++)
                wmma::load_matrix_sync(a[mi], Ast + (warp_m * 32 + mi * 16) * LDT + kk * 16, LDT);
#pragma unroll
            for (int ni = 0; ni < 4; ni++)
                wmma::load_matrix_sync(b[ni], Bst + (warp_n * 64 + ni * 16) * LDT + kk * 16, LDT);
#pragma unroll
            for (int mi = 0; mi < 2; mi++)
#pragma unroll
                for (int ni = 0; ni < 4; ni++)
                    wmma::mma_sync(c[mi][ni], a[mi], b[ni], c[mi][ni]);
        }
        __syncthreads();
    }

    // epilogue via per-warp smem scratch (32x68 f32, ldm=68 legal mult-of-4)
    float* scr = reinterpret_cast<float*>(smraw) + wid * (32 * 68);
#pragma unroll
    for (int mi = 0; mi < 2; mi++)
#pragma unroll
        for (int ni = 0; ni < 4; ni++)
            wmma::store_matrix_sync(scr + mi * 16 * 68 + ni * 16, c[mi][ni], 68, wmma::mem_row_major);
    __syncwarp();

#pragma unroll
    for (int cc = 0; cc < 2; cc++) {
        const int col = bn0 + warp_n * 64 + cc * 32 + lane;
#pragma unroll
        for (int rr = 0; rr < 32; rr++) {
            const size_t row = (size_t)(bm0 + warp_m * 32 + rr);
            float v = scr[rr * 68 + cc * 32 + lane];
            if (BN_RELU) {
                v = fmaxf(fmaf(v, sc[col], sh[col]), 0.f);
                __nv_bfloat16 h = __float2bfloat16(v);
                Chi[row * N_TOT + col] = h;
                Clo[row * N_TOT + col] = __float2bfloat16(v - __bfloat162float(h));
            } else {
                Cf[row * N_TOT + col] = v;
            }
        }
    }
}

// ============================ fp32 SGEMM (fc, K=688) ============================
template<int BM, int BN, int BK, int TM, int TN>
__global__ void sgemm_kernel(int M, int N, int K,
    const float* __restrict__ A, const float* __restrict__ B,
    float* __restrict__ C, int ldc,
    const float* __restrict__ sc, const float* __restrict__ sh)
{
    constexpr int THREADS = (BM / TM) * (BN / TN);
    __shared__ float As[BK][BM];
    __shared__ float Bs[BK][BN];
    const int tid = threadIdx.x;
    const int bn0 = blockIdx.x * BN;
    const int bm0 = blockIdx.y * BM;
    const int tx = tid % (BN / TN);
    const int ty = tid / (BN / TN);

    float acc[TM][TN];
#pragma unroll
    for (int i = 0; i < TM; i++)
#pragma unroll
        for (int j = 0; j < TN; j++) acc[i][j] = 0.f;

    constexpr int AV = BM * BK / 4 / THREADS;
    constexpr int BV = BN * BK / 4 / THREADS;

    for (int k0 = 0; k0 < K; k0 += BK) {
#pragma unroll
        for (int i = 0; i < AV; i++) {
            int idx = tid + i * THREADS;
            int r = idx / (BK / 4), c4 = idx % (BK / 4);
            float4 v = *reinterpret_cast<const float4*>(A + (size_t)(bm0 + r) * K + k0 + c4 * 4);
            As[c4 * 4 + 0][r] = v.x; As[c4 * 4 + 1][r] = v.y;
            As[c4 * 4 + 2][r] = v.z; As[c4 * 4 + 3][r] = v.w;
        }
#pragma unroll
        for (int i = 0; i < BV; i++) {
            int idx = tid + i * THREADS;
            int r = idx / (BK / 4), c4 = idx % (BK / 4);
            float4 v = *reinterpret_cast<const float4*>(B + (size_t)(bn0 + r) * K + k0 + c4 * 4);
            Bs[c4 * 4 + 0][r] = v.x; Bs[c4 * 4 + 1][r] = v.y;
            Bs[c4 * 4 + 2][r] = v.z; Bs[c4 * 4 + 3][r] = v.w;
        }
        __syncthreads();
#pragma unroll
        for (int kk = 0; kk < BK; kk++) {
            float a[TM], b[TN];
#pragma unroll
            for (int i = 0; i < TM; i += 4) {
                float4 v = *reinterpret_cast<const float4*>(&As[kk][ty * TM + i]);
                a[i] = v.x; a[i + 1] = v.y; a[i + 2] = v.z; a[i + 3] = v.w;
            }
#pragma unroll
            for (int j = 0; j < TN; j += 4) {
                float4 v = *reinterpret_cast<const float4*>(&Bs[kk][tx * TN + j]);
                b[j] = v.x; b[j + 1] = v.y; b[j + 2] = v.z; b[j + 3] = v.w;
            }
#pragma unroll
            for (int i = 0; i < TM; i++)
#pragma unroll
                for (int j = 0; j < TN; j++)
                    acc[i][j] = fmaf(a[i], b[j], acc[i][j]);
        }
        __syncthreads();
    }
#pragma unroll
    for (int i = 0; i < TM; i++) {
        int row = bm0 + ty * TM + i;
#pragma unroll
        for (int j = 0; j < TN; j++) {
            int col = bn0 + tx * TN + j;
            float v = acc[i][j];
            if (sc) v = fmaxf(fmaf(v, sc[col], sh[col]), 0.f);
            C[(size_t)row * ldc + col] = v;
        }
    }
}

// ============================ fused attention stage ============================
__global__ void attention_kernel(
    const float* __restrict__ bbox, const float* __restrict__ word,
    const float* __restrict__ Wc1, const float* __restrict__ Wc2,
    const float* __restrict__ Wsa)
{
    __shared__ float xt[10][688];
    __shared__ float rmean[10], rmax[10], att[10];
    __shared__ float csum[688], cmax[688];

    const int b = blockIdx.x;
    const int tid = threadIdx.x;

    for (int idx = tid; idx < 10 * 688; idx += blockDim.x) {
        int n = idx / 688, f = idx % 688;
        int rn = b * 10 + n;
        float v;
        if (f < 128)       v = g_obj[rn * 128 + f];
        else if (f < 132)  v = bbox[rn * 4 + (f - 128)];
        else if (f < 432)  v = word[rn * 300 + (f - 132)];
        else if (f < 560)  v = g_sen[rn * 128 + (f - 432)];
        else               v = g_bod[b * 128 + (f - 560)];
        xt[n][f] = v;
    }
    __syncthreads();

    int w = tid / 32, lane = tid % 32;
    if (w < 10) {
        float s = 0.f, mx = -3.402823e38f;
        for (int f = lane; f < 688; f += 32) {
            float v = xt[w][f];
            s += v; mx = fmaxf(mx, v);
        }
#pragma unroll
        for (int o = 16; o; o >>= 1) {
            s += __shfl_down_sync(0xffffffff, s, o);
            mx = fmaxf(mx, __shfl_down_sync(0xffffffff, mx, o));
        }
        if (lane == 0) { rmean[w] = s * (1.f / 688.f); rmax[w] = mx; }
    }
    __syncthreads();

    if (tid == 0) {
        float h[5], o1[10], o2[10];
        for (int j = 0; j < 5; j++) {
            float s = 0.f;
            for (int i = 0; i < 10; i++) s += rmean[i] * Wc1[j * 10 + i];
            h[j] = fmaxf(s, 0.f);
        }
        for (int n = 0; n < 10; n++) {
            float s = 0.f;
            for (int j = 0; j < 5; j++) s += h[j] * Wc2[n * 5 + j];
            o1[n] = s;
        }
        for (int j = 0; j < 5; j++) {
            float s = 0.f;
            for (int i = 0; i < 10; i++) s += rmax[i] * Wc1[j * 10 + i];
            h[j] = fmaxf(s, 0.f);
        }
        for (int n = 0; n < 10; n++) {
            float s = 0.f;
            for (int j = 0; j < 5; j++) s += h[j] * Wc2[n * 5 + j];
            o2[n] = s;
        }
        for (int n = 0; n < 10; n++)
            att[n] = 1.f / (1.f + expf(-(o1[n] + o2[n])));
    }
    __syncthreads();

    for (int f = tid; f < 688; f += blockDim.x) {
        float s = 0.f, mx = -3.402823e38f;
#pragma unroll
        for (int n = 0; n < 10; n++) {
            float v = xt[n][f] * att[n];
            s += v; mx = fmaxf(mx, v);
        }
        csum[f] = s; cmax[f] = mx;
    }
    __syncthreads();

    for (int f = tid; f < 688; f += blockDim.x) {
        float sa = 0.f;
#pragma unroll
        for (int j = 0; j < 7; j++) {
            int p = f + j - 3;
            if (p >= 0 && p < 688)
                sa += Wsa[j] * (csum[p] * 0.1f) + Wsa[7 + j] * cmax[p];
        }
        float sig = 1.f / (1.f + expf(-sa));
        g_xs[b * 688 + f] = csum[f] * sig;
    }
}

// ============================ launch ============================
static inline void split(const float* src, __nv_bfloat16* hi, __nv_bfloat16* lo, size_t n) {
    int n4 = (int)(n / 4);
    int blocks = (n4 + 1023) / 1024;    // 256 thr * 4 float4 each
    split_kernel<<<blocks, 256>>>((const float4*)src, (uint2*)hi, (uint2*)lo, n4);
}

extern "C" void kernel_launch(void* const* d_in, const int* in_sizes, int n_in,
                              void* d_out, int out_size)
{
    const float* feat  = (const float*)d_in[0];
    const float* bbox  = (const float*)d_in[1];
    const float* word  = (const float*)d_in[2];
    const float* sent  = (const float*)d_in[3];
    const float* body  = (const float*)d_in[4];
    const float* W1_o  = (const float*)d_in[5];
    const float* go = (const float*)d_in[6],  *bo = (const float*)d_in[7];
    const float* mo = (const float*)d_in[8],  *vo = (const float*)d_in[9];
    const float* W2_o  = (const float*)d_in[10];
    const float* W1_s  = (const float*)d_in[11];
    const float* gs = (const float*)d_in[12], *bs = (const float*)d_in[13];
    const float* ms = (const float*)d_in[14], *vs = (const float*)d_in[15];
    const float* W2_s  = (const float*)d_in[16];
    const float* W1_b  = (const float*)d_in[17];
    const float* gb = (const float*)d_in[18], *bb = (const float*)d_in[19];
    const float* mb = (const float*)d_in[20], *vb = (const float*)d_in[21];
    const float* W2_b  = (const float*)d_in[22];
    const float* Wc1   = (const float*)d_in[23];
    const float* Wc2   = (const float*)d_in[24];
    const float* Wsa   = (const float*)d_in[25];
    const float* Wf    = (const float*)d_in[26];
    const float* bias_f= (const float*)d_in[27];
    const float* gf = (const float*)d_in[28], *bfv = (const float*)d_in[29];
    const float* mf = (const float*)d_in[30], *vf = (const float*)d_in[31];

    __nv_bfloat16 *s_hi, *s_lo, *f_hi, *f_lo, *b_hi, *b_lo;
    __nv_bfloat16 *w1s_hi, *w1s_lo, *w2s_hi, *w2s_lo, *w1o_hi, *w1o_lo, *w2o_hi, *w2o_lo;
    __nv_bfloat16 *w1b_hi, *w1b_lo, *w2b_hi, *w2b_lo;
    __nv_bfloat16 *hs_hi, *hs_lo, *ho_hi, *ho_lo, *hb_hi, *hb_lo;
    float *obj, *sen, *bod, *xs;
    float *bns_s, *bns_t, *bno_s, *bno_t, *bnb_s, *bnb_t, *bnf_s, *bnf_t;
#define SYM(v, s) cudaGetSymbolAddress((void**)&v, s)
    SYM(s_hi, g_s_hi); SYM(s_lo, g_s_lo); SYM(f_hi, g_f_hi); SYM(f_lo, g_f_lo);
    SYM(b_hi, g_b_hi); SYM(b_lo, g_b_lo);
    SYM(w1s_hi, g_w1s_hi); SYM(w1s_lo, g_w1s_lo); SYM(w2s_hi, g_w2s_hi); SYM(w2s_lo, g_w2s_lo);
    SYM(w1o_hi, g_w1o_hi); SYM(w1o_lo, g_w1o_lo); SYM(w2o_hi, g_w2o_hi); SYM(w2o_lo, g_w2o_lo);
    SYM(w1b_hi, g_w1b_hi); SYM(w1b_lo, g_w1b_lo); SYM(w2b_hi, g_w2b_hi); SYM(w2b_lo, g_w2b_lo);
    SYM(hs_hi, g_hs_hi); SYM(hs_lo, g_hs_lo); SYM(ho_hi, g_ho_hi); SYM(ho_lo, g_ho_lo);
    SYM(hb_hi, g_hb_hi); SYM(hb_lo, g_hb_lo);
    SYM(obj, g_obj); SYM(sen, g_sen); SYM(bod, g_bod); SYM(xs, g_xs);
    SYM(bns_s, g_bns_s); SYM(bns_t, g_bns_t); SYM(bno_s, g_bno_s); SYM(bno_t, g_bno_t);
    SYM(bnb_s, g_bnb_s); SYM(bnb_t, g_bnb_t); SYM(bnf_s, g_bnf_s); SYM(bnf_t, g_bnf_t);
#undef SYM

    const int SMB = 4 * (128 * 72 * 2);   // 73728 B: A0|A1|B0|B1
    cudaFuncSetAttribute(wmma_gemm<4096, true>,  cudaFuncAttributeMaxDynamicSharedMemorySize, SMB);
    cudaFuncSetAttribute(wmma_gemm<1024, true>,  cudaFuncAttributeMaxDynamicSharedMemorySize, SMB);
    cudaFuncSetAttribute(wmma_gemm<2048, true>,  cudaFuncAttributeMaxDynamicSharedMemorySize, SMB);
    cudaFuncSetAttribute(wmma_gemm<512,  false>, cudaFuncAttributeMaxDynamicSharedMemorySize, SMB);
    cudaFuncSetAttribute(wmma_gemm<128,  false>, cudaFuncAttributeMaxDynamicSharedMemorySize, SMB);
    cudaFuncSetAttribute(wmma_gemm<256,  false>, cudaFuncAttributeMaxDynamicSharedMemorySize, SMB);

    prep_bn_kernel<<<1, 512>>>(gs, bs, ms, vs, go, bo, mo, vo,
                               gb, bb, mb, vb, gf, bfv, mf, vf, bias_f);

    split(sent, s_hi, s_lo, (size_t)10240 * 4096);
    split(feat, f_hi, f_lo, (size_t)10240 * 1024);
    split(body, b_hi, b_lo, (size_t)1024 * 2048);
    split(W1_s, w1s_hi, w1s_lo, (size_t)512 * 4096);
    split(W2_s, w2s_hi, w2s_lo, (size_t)128 * 512);
    split(W1_o, w1o_hi, w1o_lo, (size_t)128 * 1024);
    split(W2_o, w2o_hi, w2o_lo, (size_t)128 * 128);
    split(W1_b, w1b_hi, w1b_lo, (size_t)256 * 2048);
    split(W2_b, w2b_hi, w2b_lo, (size_t)128 * 256);

    // GEMM1s (fused BN+ReLU, write bf16 hi/lo hidden)
    wmma_gemm<4096, true><<<dim3(512 / 128, 10240 / 128), 256, SMB>>>(512,
        s_hi, s_lo, w1s_hi, w1s_lo, nullptr, hs_hi, hs_lo, bns_s, bns_t);
    wmma_gemm<1024, true><<<dim3(128 / 128, 10240 / 128), 256, SMB>>>(128,
        f_hi, f_lo, w1o_hi, w1o_lo, nullptr, ho_hi, ho_lo, bno_s, bno_t);
    wmma_gemm<2048, true><<<dim3(256 / 128, 1024 / 128), 256, SMB>>>(256,
        b_hi, b_lo, w1b_hi, w1b_lo, nullptr, hb_hi, hb_lo, bnb_s, bnb_t);

    // GEMM2s (fp32 out)
    wmma_gemm<512, false><<<dim3(1, 10240 / 128), 256, SMB>>>(128,
        hs_hi, hs_lo, w2s_hi, w2s_lo, sen, nullptr, nullptr, nullptr, nullptr);
    wmma_gemm<128, false><<<dim3(1, 10240 / 128), 256, SMB>>>(128,
        ho_hi, ho_lo, w2o_hi, w2o_lo, obj, nullptr, nullptr, nullptr, nullptr);
    wmma_gemm<256, false><<<dim3(1, 1024 / 128), 256, SMB>>>(128,
        hb_hi, hb_lo, w2b_hi, w2b_lo, bod, nullptr, nullptr, nullptr, nullptr);

    attention_kernel<<<1024, 320>>>(bbox, word, Wc1, Wc2, Wsa);

    // fc: [1024,688] @ [688,256] + bias + BN + relu (fp32, K=688)
    sgemm_kernel<64, 64, 16, 4, 4><<<dim3(256 / 64, 1024 / 64), 256>>>(
        1024, 256, 688, xs, Wf, (float*)d_out, 256, bnf_s, bnf_t);
}

// round 8
// speedup vs baseline: 1.0895x; 1.0895x over previous
#include <cuda_runtime.h>
#include <cuda_bf16.h>
#include <mma.h>
#include <math.h>
#include <stdint.h>

using namespace nvcuda;

#define BN_EPS 1e-5f

// ============================ scratch (device globals) ============================
__device__ __nv_bfloat16 g_w1s_hi[512 * 4096], g_w1s_lo[512 * 4096];
__device__ __nv_bfloat16 g_w2s_hi[128 * 512],  g_w2s_lo[128 * 512];
__device__ __nv_bfloat16 g_w1o_hi[128 * 1024], g_w1o_lo[128 * 1024];
__device__ __nv_bfloat16 g_w2o_hi[128 * 128],  g_w2o_lo[128 * 128];
__device__ __nv_bfloat16 g_w1b_hi[256 * 2048], g_w1b_lo[256 * 2048];
__device__ __nv_bfloat16 g_w2b_hi[128 * 256],  g_w2b_lo[128 * 256];
__device__ __nv_bfloat16 g_hs_hi[10240 * 512], g_hs_lo[10240 * 512];
__device__ __nv_bfloat16 g_ho_hi[10240 * 128], g_ho_lo[10240 * 128];
__device__ __nv_bfloat16 g_hb_hi[1024 * 256],  g_hb_lo[1024 * 256];
__device__ float g_obj[10240 * 128];
__device__ float g_sen[10240 * 128];
__device__ float g_bod[1024 * 128];
__device__ float g_xs[1024 * 688];
__device__ float g_bns_s[512], g_bns_t[512];
__device__ float g_bno_s[128], g_bno_t[128];
__device__ float g_bnb_s[256], g_bnb_t[256];
__device__ float g_bnf_s[256], g_bnf_t[256];

// ============================ helpers ============================
__device__ __forceinline__ void cp_async16(uint32_t saddr, const void* gptr) {
    asm volatile("cp.async.cg.shared.global [%0], [%1], 16;" :: "r"(saddr), "l"(gptr));
}
__device__ __forceinline__ uint32_t smem_u32(const void* p) {
    uint32_t a;
    asm("{ .reg .u64 t; cvta.to.shared.u64 t, %1; cvt.u32.u64 %0, t; }" : "=r"(a) : "l"(p));
    return a;
}
__device__ __forceinline__ void cp_commit() {
    asm volatile("cp.async.commit_group;" ::: "memory");
}
template<int N>
__device__ __forceinline__ void cp_wait() {
    asm volatile("cp.async.wait_group %0;" :: "n"(N) : "memory");
}

// ============================ BN fold prep ============================
__global__ void prep_bn_kernel(
    const float* __restrict__ gs, const float* __restrict__ bs,
    const float* __restrict__ ms, const float* __restrict__ vs,
    const float* __restrict__ go, const float* __restrict__ bo,
    const float* __restrict__ mo, const float* __restrict__ vo,
    const float* __restrict__ gb, const float* __restrict__ bb,
    const float* __restrict__ mb, const float* __restrict__ vb,
    const float* __restrict__ gf, const float* __restrict__ bfv,
    const float* __restrict__ mf, const float* __restrict__ vf,
    const float* __restrict__ bias_f)
{
    int i = threadIdx.x;
    if (i < 512) { float s = gs[i] * rsqrtf(vs[i] + BN_EPS); g_bns_s[i] = s; g_bns_t[i] = bs[i] - ms[i] * s; }
    if (i < 128) { float s = go[i] * rsqrtf(vo[i] + BN_EPS); g_bno_s[i] = s; g_bno_t[i] = bo[i] - mo[i] * s; }
    if (i < 256) { float s = gb[i] * rsqrtf(vb[i] + BN_EPS); g_bnb_s[i] = s; g_bnb_t[i] = bb[i] - mb[i] * s; }
    if (i < 256) { float s = gf[i] * rsqrtf(vf[i] + BN_EPS); g_bnf_s[i] = s; g_bnf_t[i] = (bias_f[i] - mf[i]) * s + bfv[i]; }
}

// ============================ fp32 -> bf16 hi/lo split (weights only) ============================
__global__ void split_kernel(const float4* __restrict__ src,
                             uint2* __restrict__ hi, uint2* __restrict__ lo, int n4)
{
    int i = blockIdx.x * blockDim.x + threadIdx.x;
    if (i >= n4) return;
    float4 v = src[i];
    union { __nv_bfloat16 h[4]; uint2 u; } H, L;
    H.h[0] = __float2bfloat16(v.x); L.h[0] = __float2bfloat16(v.x - __bfloat162float(H.h[0]));
    H.h[1] = __float2bfloat16(v.y); L.h[1] = __float2bfloat16(v.y - __bfloat162float(H.h[1]));
    H.h[2] = __float2bfloat16(v.z); L.h[2] = __float2bfloat16(v.z - __bfloat162float(H.h[2]));
    H.h[3] = __float2bfloat16(v.w); L.h[3] = __float2bfloat16(v.w - __bfloat162float(H.h[3]));
    hi[i] = H.u; lo[i] = L.u;
}

// ============================ fused-split wmma bf16x3 GEMM (GEMM1) ============================
// C = A32[M,K] @ (Bhi+Blo)[N_TOT,K]^T with A split to hi/lo IN-KERNEL per K-chunk.
// Per 64-wide chunk: acc += Ahi*Bhi + Alo*Bhi + Ahi*Blo  (K-major 3-term).
// grid = (N_TOT/128, M/128), 256 threads, 8 warps 4x2, warp tile 32x64.
template<int K, bool BN_RELU>
__global__ __launch_bounds__(256)
void fgemm(int N_TOT,
    const float* __restrict__ A32,
    const __nv_bfloat16* __restrict__ Bhi, const __nv_bfloat16* __restrict__ Blo,
    float* __restrict__ Cf,
    __nv_bfloat16* __restrict__ Chi, __nv_bfloat16* __restrict__ Clo,
    const float* __restrict__ sc, const float* __restrict__ sh)
{
    constexpr int KITERS = K / 64;
    constexpr int LDT = 72;               // 144B stride: 16B multiple
    constexpr int PL = 128 * LDT * 2;     // 18432 B per plane
    // planes: Ahi | Alo | Bhi0 | Blo0 | Bhi1 | Blo1 = 110592 B; epi scratch (69632) unions at 0
    extern __shared__ __align__(16) char smraw[];
    const uint32_t sbase = smem_u32(smraw);

    const int tid = threadIdx.x;
    const int wid = tid >> 5;
    const int lane = tid & 31;
    const int warp_m = wid & 3;
    const int warp_n = wid >> 2;
    const int bm0 = blockIdx.y * 128;
    const int bn0 = blockIdx.x * 128;

    wmma::fragment<wmma::accumulator, 16, 16, 16, float> c[2][4];
#pragma unroll
    for (int mi = 0; mi < 2; mi++)
#pragma unroll
        for (int ni = 0; ni < 4; ni++) wmma::fill_fragment(c[mi][ni], 0.0f);

    const int lr = tid >> 3;      // row 0..31 (+32*i)
    const int lq = tid & 7;       // 8-float segment in 64-col chunk

    float4 areg[8];               // prefetched A fp32: 4 rows x 8 floats

    auto ldgA = [&](int cix) {
#pragma unroll
        for (int i = 0; i < 4; i++) {
            const float* p = A32 + (size_t)(bm0 + lr + i * 32) * K + cix * 64 + lq * 8;
            areg[i * 2]     = *reinterpret_cast<const float4*>(p);
            areg[i * 2 + 1] = *reinterpret_cast<const float4*>(p + 4);
        }
    };
    auto cpB = [&](int cix, int s) {
        const uint32_t bh = sbase + 2 * PL + s * 2 * PL;
        const uint32_t bl = bh + PL;
#pragma unroll
        for (int i = 0; i < 4; i++) {
            int r = lr + i * 32;
            cp_async16(bh + r * (LDT * 2) + lq * 16, Bhi + (size_t)(bn0 + r) * K + cix * 64 + lq * 8);
            cp_async16(bl + r * (LDT * 2) + lq * 16, Blo + (size_t)(bn0 + r) * K + cix * 64 + lq * 8);
        }
        cp_commit();
    };
    auto stsA = [&]() {
#pragma unroll
        for (int i = 0; i < 4; i++) {
            int r = lr + i * 32;
            float f[8] = { areg[i*2].x, areg[i*2].y, areg[i*2].z, areg[i*2].w,
                           areg[i*2+1].x, areg[i*2+1].y, areg[i*2+1].z, areg[i*2+1].w };
            union { __nv_bfloat16 h[8]; uint4 u; } H, L;
#pragma unroll
            for (int j = 0; j < 8; j++) {
                H.h[j] = __float2bfloat16(f[j]);
                L.h[j] = __float2bfloat16(f[j] - __bfloat162float(H.h[j]));
            }
            *reinterpret_cast<uint4*>(smraw + r * (LDT * 2) + lq * 16) = H.u;
            *reinterpret_cast<uint4*>(smraw + PL + r * (LDT * 2) + lq * 16) = L.u;
        }
    };

    ldgA(0);
    cpB(0, 0);
    for (int cix = 0; cix < KITERS; ++cix) {
        const int s = cix & 1;
        __syncthreads();            // all warps done reading planes from prev chunk
        stsA();                     // fill Ahi/Alo for chunk cix
        if (cix + 1 < KITERS) {
            ldgA(cix + 1);          // prefetch next A (latency hidden under mma)
            cpB(cix + 1, s ^ 1);
            cp_wait<1>();           // B(s) complete
        } else {
            cp_wait<0>();
        }
        __syncthreads();            // A planes + B(s) visible

        const __nv_bfloat16* ah = reinterpret_cast<const __nv_bfloat16*>(smraw);
        const __nv_bfloat16* al = reinterpret_cast<const __nv_bfloat16*>(smraw + PL);
        const __nv_bfloat16* bh = reinterpret_cast<const __nv_bfloat16*>(smraw + 2 * PL + s * 2 * PL);
        const __nv_bfloat16* bl = reinterpret_cast<const __nv_bfloat16*>(smraw + 2 * PL + s * 2 * PL + PL);
#pragma unroll
        for (int kk = 0; kk < 4; kk++) {
            wmma::fragment<wmma::matrix_a, 16, 16, 16, __nv_bfloat16, wmma::row_major> a_hi[2], a_lo[2];
            wmma::fragment<wmma::matrix_b, 16, 16, 16, __nv_bfloat16, wmma::col_major> b_hi[4], b_lo[4];
#pragma unroll
            for (int mi = 0; mi < 2; mi++) {
                wmma::load_matrix_sync(a_hi[mi], ah + (warp_m * 32 + mi * 16) * LDT + kk * 16, LDT);
                wmma::load_matrix_sync(a_lo[mi], al + (warp_m * 32 + mi * 16) * LDT + kk * 16, LDT);
            }
#pragma unroll
            for (int ni = 0; ni < 4; ni++) {
                wmma::load_matrix_sync(b_hi[ni], bh + (warp_n * 64 + ni * 16) * LDT + kk * 16, LDT);
                wmma::load_matrix_sync(b_lo[ni], bl + (warp_n * 64 + ni * 16) * LDT + kk * 16, LDT);
            }
#pragma unroll
            for (int mi = 0; mi < 2; mi++)
#pragma unroll
                for (int ni = 0; ni < 4; ni++) {
                    wmma::mma_sync(c[mi][ni], a_hi[mi], b_hi[ni], c[mi][ni]);
                    wmma::mma_sync(c[mi][ni], a_lo[mi], b_hi[ni], c[mi][ni]);
                    wmma::mma_sync(c[mi][ni], a_hi[mi], b_lo[ni], c[mi][ni]);
                }
        }
    }
    __syncthreads();

    float* scr = reinterpret_cast<float*>(smraw) + wid * (32 * 68);
#pragma unroll
    for (int mi = 0; mi < 2; mi++)
#pragma unroll
        for (int ni = 0; ni < 4; ni++)
            wmma::store_matrix_sync(scr + mi * 16 * 68 + ni * 16, c[mi][ni], 68, wmma::mem_row_major);
    __syncwarp();

#pragma unroll
    for (int cc = 0; cc < 2; cc++) {
        const int col = bn0 + warp_n * 64 + cc * 32 + lane;
#pragma unroll
        for (int rr = 0; rr < 32; rr++) {
            const size_t row = (size_t)(bm0 + warp_m * 32 + rr);
            float v = scr[rr * 68 + cc * 32 + lane];
            if (BN_RELU) {
                v = fmaxf(fmaf(v, sc[col], sh[col]), 0.f);
                __nv_bfloat16 h = __float2bfloat16(v);
                Chi[row * N_TOT + col] = h;
                Clo[row * N_TOT + col] = __float2bfloat16(v - __bfloat162float(h));
            } else {
                Cf[row * N_TOT + col] = v;
            }
        }
    }
}

// ============================ pre-split wmma bf16x3 GEMM (GEMM2) ============================
template<int K, bool BN_RELU>
__global__ __launch_bounds__(256)
void wmma_gemm(int N_TOT,
    const __nv_bfloat16* __restrict__ Ahi, const __nv_bfloat16* __restrict__ Alo,
    const __nv_bfloat16* __restrict__ Bhi, const __nv_bfloat16* __restrict__ Blo,
    float* __restrict__ Cf,
    __nv_bfloat16* __restrict__ Chi, __nv_bfloat16* __restrict__ Clo,
    const float* __restrict__ sc, const float* __restrict__ sh)
{
    constexpr int KITERS = K / 64;
    constexpr int TOTAL = 3 * KITERS;
    constexpr int LDT = 72;
    constexpr int A_STG = 128 * LDT * 2;
    constexpr int B_STG = 128 * LDT * 2;
    extern __shared__ __align__(16) char smraw[];
    const uint32_t sbase = smem_u32(smraw);

    const int tid = threadIdx.x;
    const int wid = tid >> 5;
    const int lane = tid & 31;
    const int warp_m = wid & 3;
    const int warp_n = wid >> 2;
    const int bm0 = blockIdx.y * 128;
    const int bn0 = blockIdx.x * 128;

    wmma::fragment<wmma::accumulator, 16, 16, 16, float> c[2][4];
#pragma unroll
    for (int mi = 0; mi < 2; mi++)
#pragma unroll
        for (int ni = 0; ni < 4; ni++) wmma::fill_fragment(c[mi][ni], 0.0f);

    const int lr = tid >> 3;
    const int lq = tid & 7;

    auto load_stage = [&](int it, int stage) {
        const int t = it / KITERS, cix = it % KITERS;
        const __nv_bfloat16* Ap = (t == 1) ? Alo : Ahi;
        const __nv_bfloat16* Bp = (t == 2) ? Blo : Bhi;
        const uint32_t abase = sbase + stage * A_STG;
        const uint32_t bbase = sbase + 2 * A_STG + stage * B_STG;
#pragma unroll
        for (int i = 0; i < 4; i++) {
            int r = lr + i * 32;
            cp_async16(abase + r * (LDT * 2) + lq * 16,
                       Ap + (size_t)(bm0 + r) * K + cix * 64 + lq * 8);
        }
#pragma unroll
        for (int i = 0; i < 4; i++) {
            int r = lr + i * 32;
            cp_async16(bbase + r * (LDT * 2) + lq * 16,
                       Bp + (size_t)(bn0 + r) * K + cix * 64 + lq * 8);
        }
        cp_commit();
    };

    __nv_bfloat16* As = reinterpret_cast<__nv_bfloat16*>(smraw);
    __nv_bfloat16* Bs = reinterpret_cast<__nv_bfloat16*>(smraw + 2 * A_STG);

    load_stage(0, 0);
    for (int it = 0; it < TOTAL; ++it) {
        const int stage = it & 1;
        if (it + 1 < TOTAL) {
            load_stage(it + 1, stage ^ 1);
            cp_wait<1>();
        } else {
            cp_wait<0>();
        }
        __syncthreads();

        const __nv_bfloat16* Ast = As + stage * (128 * LDT);
        const __nv_bfloat16* Bst = Bs + stage * (128 * LDT);
#pragma unroll
        for (int kk = 0; kk < 4; kk++) {
            wmma::fragment<wmma::matrix_a, 16, 16, 16, __nv_bfloat16, wmma::row_major> a[2];
            wmma::fragment<wmma::matrix_b, 16, 16, 16, __nv_bfloat16, wmma::col_major> b[4];
#pragma unroll
            for (int mi = 0; mi < 2; mi++)
                wmma::load_matrix_sync(a[mi], Ast + (warp_m * 32 + mi * 16) * LDT + kk * 16, LDT);
#pragma unroll
            for (int ni = 0; ni < 4; ni++)
                wmma::load_matrix_sync(b[ni], Bst + (warp_n * 64 + ni * 16) * LDT + kk * 16, LDT);
#pragma unroll
            for (int mi = 0; mi < 2; mi++)
#pragma unroll
                for (int ni = 0; ni < 4; ni++)
                    wmma::mma_sync(c[mi][ni], a[mi], b[ni], c[mi][ni]);
        }
        __syncthreads();
    }

    float* scr = reinterpret_cast<float*>(smraw) + wid * (32 * 68);
#pragma unroll
    for (int mi = 0; mi < 2; mi++)
#pragma unroll
        for (int ni = 0; ni < 4; ni++)
            wmma::store_matrix_sync(scr + mi * 16 * 68 + ni * 16, c[mi][ni], 68, wmma::mem_row_major);
    __syncwarp();

#pragma unroll
    for (int cc = 0; cc < 2; cc++) {
        const int col = bn0 + warp_n * 64 + cc * 32 + lane;
#pragma unroll
        for (int rr = 0; rr < 32; rr++) {
            const size_t row = (size_t)(bm0 + warp_m * 32 + rr);
            float v = scr[rr * 68 + cc * 32 + lane];
            if (BN_RELU) {
                v = fmaxf(fmaf(v, sc[col], sh[col]), 0.f);
                __nv_bfloat16 h = __float2bfloat16(v);
                Chi[row * N_TOT + col] = h;
                Clo[row * N_TOT + col] = __float2bfloat16(v - __bfloat162float(h));
            } else {
                Cf[row * N_TOT + col] = v;
            }
        }
    }
}

// ============================ fp32 SGEMM (fc, K=688) ============================
template<int BM, int BN, int BK, int TM, int TN>
__global__ void sgemm_kernel(int M, int N, int K,
    const float* __restrict__ A, const float* __restrict__ B,
    float* __restrict__ C, int ldc,
    const float* __restrict__ sc, const float* __restrict__ sh)
{
    constexpr int THREADS = (BM / TM) * (BN / TN);
    __shared__ float As[BK][BM];
    __shared__ float Bs[BK][BN];
    const int tid = threadIdx.x;
    const int bn0 = blockIdx.x * BN;
    const int bm0 = blockIdx.y * BM;
    const int tx = tid % (BN / TN);
    const int ty = tid / (BN / TN);

    float acc[TM][TN];
#pragma unroll
    for (int i = 0; i < TM; i++)
#pragma unroll
        for (int j = 0; j < TN; j++) acc[i][j] = 0.f;

    constexpr int AV = BM * BK / 4 / THREADS;
    constexpr int BV = BN * BK / 4 / THREADS;

    for (int k0 = 0; k0 < K; k0 += BK) {
#pragma unroll
        for (int i = 0; i < AV; i++) {
            int idx = tid + i * THREADS;
            int r = idx / (BK / 4), c4 = idx % (BK / 4);
            float4 v = *reinterpret_cast<const float4*>(A + (size_t)(bm0 + r) * K + k0 + c4 * 4);
            As[c4 * 4 + 0][r] = v.x; As[c4 * 4 + 1][r] = v.y;
            As[c4 * 4 + 2][r] = v.z; As[c4 * 4 + 3][r] = v.w;
        }
#pragma unroll
        for (int i = 0; i < BV; i++) {
            int idx = tid + i * THREADS;
            int r = idx / (BK / 4), c4 = idx % (BK / 4);
            float4 v = *reinterpret_cast<const float4*>(B + (size_t)(bn0 + r) * K + k0 + c4 * 4);
            Bs[c4 * 4 + 0][r] = v.x; Bs[c4 * 4 + 1][r] = v.y;
            Bs[c4 * 4 + 2][r] = v.z; Bs[c4 * 4 + 3][r] = v.w;
        }
        __syncthreads();
#pragma unroll
        for (int kk = 0; kk < BK; kk++) {
            float a[TM], b[TN];
#pragma unroll
            for (int i = 0; i < TM; i += 4) {
                float4 v = *reinterpret_cast<const float4*>(&As[kk][ty * TM + i]);
                a[i] = v.x; a[i + 1] = v.y; a[i + 2] = v.z; a[i + 3] = v.w;
            }
#pragma unroll
            for (int j = 0; j < TN; j += 4) {
                float4 v = *reinterpret_cast<const float4*>(&Bs[kk][tx * TN + j]);
                b[j] = v.x; b[j + 1] = v.y; b[j + 2] = v.z; b[j + 3] = v.w;
            }
#pragma unroll
            for (int i = 0; i < TM; i++)
#pragma unroll
                for (int j = 0; j < TN; j++)
                    acc[i][j] = fmaf(a[i], b[j], acc[i][j]);
        }
        __syncthreads();
    }
#pragma unroll
    for (int i = 0; i < TM; i++) {
        int row = bm0 + ty * TM + i;
#pragma unroll
        for (int j = 0; j < TN; j++) {
            int col = bn0 + tx * TN + j;
            float v = acc[i][j];
            if (sc) v = fmaxf(fmaf(v, sc[col], sh[col]), 0.f);
            C[(size_t)row * ldc + col] = v;
        }
    }
}

// ============================ fused attention stage ============================
__global__ void attention_kernel(
    const float* __restrict__ bbox, const float* __restrict__ word,
    const float* __restrict__ Wc1, const float* __restrict__ Wc2,
    const float* __restrict__ Wsa)
{
    __shared__ float xt[10][688];
    __shared__ float rmean[10], rmax[10], att[10];
    __shared__ float csum[688], cmax[688];

    const int b = blockIdx.x;
    const int tid = threadIdx.x;

    for (int idx = tid; idx < 10 * 688; idx += blockDim.x) {
        int n = idx / 688, f = idx % 688;
        int rn = b * 10 + n;
        float v;
        if (f < 128)       v = g_obj[rn * 128 + f];
        else if (f < 132)  v = bbox[rn * 4 + (f - 128)];
        else if (f < 432)  v = word[rn * 300 + (f - 132)];
        else if (f < 560)  v = g_sen[rn * 128 + (f - 432)];
        else               v = g_bod[b * 128 + (f - 560)];
        xt[n][f] = v;
    }
    __syncthreads();

    int w = tid / 32, lane = tid % 32;
    if (w < 10) {
        float s = 0.f, mx = -3.402823e38f;
        for (int f = lane; f < 688; f += 32) {
            float v = xt[w][f];
            s += v; mx = fmaxf(mx, v);
        }
#pragma unroll
        for (int o = 16; o; o >>= 1) {
            s += __shfl_down_sync(0xffffffff, s, o);
            mx = fmaxf(mx, __shfl_down_sync(0xffffffff, mx, o));
        }
        if (lane == 0) { rmean[w] = s * (1.f / 688.f); rmax[w] = mx; }
    }
    __syncthreads();

    if (tid == 0) {
        float h[5], o1[10], o2[10];
        for (int j = 0; j < 5; j++) {
            float s = 0.f;
            for (int i = 0; i < 10; i++) s += rmean[i] * Wc1[j * 10 + i];
            h[j] = fmaxf(s, 0.f);
        }
        for (int n = 0; n < 10; n++) {
            float s = 0.f;
            for (int j = 0; j < 5; j++) s += h[j] * Wc2[n * 5 + j];
            o1[n] = s;
        }
        for (int j = 0; j < 5; j++) {
            float s = 0.f;
            for (int i = 0; i < 10; i++) s += rmax[i] * Wc1[j * 10 + i];
            h[j] = fmaxf(s, 0.f);
        }
        for (int n = 0; n < 10; n++) {
            float s = 0.f;
            for (int j = 0; j < 5; j++) s += h[j] * Wc2[n * 5 + j];
            o2[n] = s;
        }
        for (int n = 0; n < 10; n++)
            att[n] = 1.f / (1.f + expf(-(o1[n] + o2[n])));
    }
    __syncthreads();

    for (int f = tid; f < 688; f += blockDim.x) {
        float s = 0.f, mx = -3.402823e38f;
#pragma unroll
        for (int n = 0; n < 10; n++) {
            float v = xt[n][f] * att[n];
            s += v; mx = fmaxf(mx, v);
        }
        csum[f] = s; cmax[f] = mx;
    }
    __syncthreads();

    for (int f = tid; f < 688; f += blockDim.x) {
        float sa = 0.f;
#pragma unroll
        for (int j = 0; j < 7; j++) {
            int p = f + j - 3;
            if (p >= 0 && p < 688)
                sa += Wsa[j] * (csum[p] * 0.1f) + Wsa[7 + j] * cmax[p];
        }
        float sig = 1.f / (1.f + expf(-sa));
        g_xs[b * 688 + f] = csum[f] * sig;
    }
}

// ============================ launch ============================
static inline void split(const float* src, __nv_bfloat16* hi, __nv_bfloat16* lo, size_t n) {
    int n4 = (int)(n / 4);
    split_kernel<<<(n4 + 255) / 256, 256>>>((const float4*)src, (uint2*)hi, (uint2*)lo, n4);
}

extern "C" void kernel_launch(void* const* d_in, const int* in_sizes, int n_in,
                              void* d_out, int out_size)
{
    const float* feat  = (const float*)d_in[0];
    const float* bbox  = (const float*)d_in[1];
    const float* word  = (const float*)d_in[2];
    const float* sent  = (const float*)d_in[3];
    const float* body  = (const float*)d_in[4];
    const float* W1_o  = (const float*)d_in[5];
    const float* go = (const float*)d_in[6],  *bo = (const float*)d_in[7];
    const float* mo = (const float*)d_in[8],  *vo = (const float*)d_in[9];
    const float* W2_o  = (const float*)d_in[10];
    const float* W1_s  = (const float*)d_in[11];
    const float* gs = (const float*)d_in[12], *bs = (const float*)d_in[13];
    const float* ms = (const float*)d_in[14], *vs = (const float*)d_in[15];
    const float* W2_s  = (const float*)d_in[16];
    const float* W1_b  = (const float*)d_in[17];
    const float* gb = (const float*)d_in[18], *bb = (const float*)d_in[19];
    const float* mb = (const float*)d_in[20], *vb = (const float*)d_in[21];
    const float* W2_b  = (const float*)d_in[22];
    const float* Wc1   = (const float*)d_in[23];
    const float* Wc2   = (const float*)d_in[24];
    const float* Wsa   = (const float*)d_in[25];
    const float* Wf    = (const float*)d_in[26];
    const float* bias_f= (const float*)d_in[27];
    const float* gf = (const float*)d_in[28], *bfv = (const float*)d_in[29];
    const float* mf = (const float*)d_in[30], *vf = (const float*)d_in[31];

    __nv_bfloat16 *w1s_hi, *w1s_lo, *w2s_hi, *w2s_lo, *w1o_hi, *w1o_lo, *w2o_hi, *w2o_lo;
    __nv_bfloat16 *w1b_hi, *w1b_lo, *w2b_hi, *w2b_lo;
    __nv_bfloat16 *hs_hi, *hs_lo, *ho_hi, *ho_lo, *hb_hi, *hb_lo;
    float *obj, *sen, *bod, *xs;
    float *bns_s, *bns_t, *bno_s, *bno_t, *bnb_s, *bnb_t, *bnf_s, *bnf_t;
#define SYM(v, s) cudaGetSymbolAddress((void**)&v, s)
    SYM(w1s_hi, g_w1s_hi); SYM(w1s_lo, g_w1s_lo); SYM(w2s_hi, g_w2s_hi); SYM(w2s_lo, g_w2s_lo);
    SYM(w1o_hi, g_w1o_hi); SYM(w1o_lo, g_w1o_lo); SYM(w2o_hi, g_w2o_hi); SYM(w2o_lo, g_w2o_lo);
    SYM(w1b_hi, g_w1b_hi); SYM(w1b_lo, g_w1b_lo); SYM(w2b_hi, g_w2b_hi); SYM(w2b_lo, g_w2b_lo);
    SYM(hs_hi, g_hs_hi); SYM(hs_lo, g_hs_lo); SYM(ho_hi, g_ho_hi); SYM(ho_lo, g_ho_lo);
    SYM(hb_hi, g_hb_hi); SYM(hb_lo, g_hb_lo);
    SYM(obj, g_obj); SYM(sen, g_sen); SYM(bod, g_bod); SYM(xs, g_xs);
    SYM(bns_s, g_bns_s); SYM(bns_t, g_bns_t); SYM(bno_s, g_bno_s); SYM(bno_t, g_bno_t);
    SYM(bnb_s, g_bnb_s); SYM(bnb_t, g_bnb_t); SYM(bnf_s, g_bnf_s); SYM(bnf_t, g_bnf_t);
#undef SYM

    const int SMF = 6 * (128 * 72 * 2);   // 110592 B (fused GEMM1)
    const int SMB = 4 * (128 * 72 * 2);   // 73728 B (GEMM2)
    cudaFuncSetAttribute(fgemm<4096, true>, cudaFuncAttributeMaxDynamicSharedMemorySize, SMF);
    cudaFuncSetAttribute(fgemm<1024, true>, cudaFuncAttributeMaxDynamicSharedMemorySize, SMF);
    cudaFuncSetAttribute(fgemm<2048, true>, cudaFuncAttributeMaxDynamicSharedMemorySize, SMF);
    cudaFuncSetAttribute(wmma_gemm<512, false>, cudaFuncAttributeMaxDynamicSharedMemorySize, SMB);
    cudaFuncSetAttribute(wmma_gemm<128, false>, cudaFuncAttributeMaxDynamicSharedMemorySize, SMB);
    cudaFuncSetAttribute(wmma_gemm<256, false>, cudaFuncAttributeMaxDynamicSharedMemorySize, SMB);

    prep_bn_kernel<<<1, 512>>>(gs, bs, ms, vs, go, bo, mo, vo,
                               gb, bb, mb, vb, gf, bfv, mf, vf, bias_f);

    // weight splits only (activations are split in-kernel now)
    split(W1_s, w1s_hi, w1s_lo, (size_t)512 * 4096);
    split(W2_s, w2s_hi, w2s_lo, (size_t)128 * 512);
    split(W1_o, w1o_hi, w1o_lo, (size_t)128 * 1024);
    split(W2_o, w2o_hi, w2o_lo, (size_t)128 * 128);
    split(W1_b, w1b_hi, w1b_lo, (size_t)256 * 2048);
    split(W2_b, w2b_hi, w2b_lo, (size_t)128 * 256);

    // GEMM1s: fused fp32->bf16x3, BN+ReLU epilogue writing hidden hi/lo
    fgemm<4096, true><<<dim3(4, 80), 256, SMF>>>(512,
        sent, w1s_hi, w1s_lo, nullptr, hs_hi, hs_lo, bns_s, bns_t);
    fgemm<1024, true><<<dim3(1, 80), 256, SMF>>>(128,
        feat, w1o_hi, w1o_lo, nullptr, ho_hi, ho_lo, bno_s, bno_t);
    fgemm<2048, true><<<dim3(2, 8), 256, SMF>>>(256,
        body, w1b_hi, w1b_lo, nullptr, hb_hi, hb_lo, bnb_s, bnb_t);

    // GEMM2s (pre-split hidden planes, fp32 out)
    wmma_gemm<512, false><<<dim3(1, 80), 256, SMB>>>(128,
        hs_hi, hs_lo, w2s_hi, w2s_lo, sen, nullptr, nullptr, nullptr, nullptr);
    wmma_gemm<128, false><<<dim3(1, 80), 256, SMB>>>(128,
        ho_hi, ho_lo, w2o_hi, w2o_lo, obj, nullptr, nullptr, nullptr, nullptr);
    wmma_gemm<256, false><<<dim3(1, 8), 256, SMB>>>(128,
        hb_hi, hb_lo, w2b_hi, w2b_lo, bod, nullptr, nullptr, nullptr, nullptr);

    attention_kernel<<<1024, 320>>>(bbox, word, Wc1, Wc2, Wsa);

    // fc: [1024,688] @ [688,256] + bias + BN + relu
    sgemm_kernel<64, 64, 16, 4, 4><<<dim3(256 / 64, 1024 / 64), 256>>>(
        1024, 256, 688, xs, Wf, (float*)d_out, 256, bnf_s, bnf_t);
}

// round 9
// speedup vs baseline: 1.4470x; 1.3282x over previous
#include <cuda_runtime.h>
#include <cuda_bf16.h>
#include <mma.h>
#include <math.h>
#include <stdint.h>

using namespace nvcuda;

#define BN_EPS 1e-5f

// ============================ scratch (device globals) ============================
__device__ __nv_bfloat16 g_w1s_hi[512 * 4096], g_w1s_lo[512 * 4096];
__device__ __nv_bfloat16 g_w2s_hi[128 * 512],  g_w2s_lo[128 * 512];
__device__ __nv_bfloat16 g_w1o_hi[128 * 1024], g_w1o_lo[128 * 1024];
__device__ __nv_bfloat16 g_w2o_hi[128 * 128],  g_w2o_lo[128 * 128];
__device__ __nv_bfloat16 g_w1b_hi[256 * 2048], g_w1b_lo[256 * 2048];
__device__ __nv_bfloat16 g_w2b_hi[128 * 256],  g_w2b_lo[128 * 256];
__device__ __nv_bfloat16 g_hs_hi[10240 * 512], g_hs_lo[10240 * 512];
__device__ __nv_bfloat16 g_ho_hi[10240 * 128], g_ho_lo[10240 * 128];
__device__ __nv_bfloat16 g_hb_hi[1024 * 256],  g_hb_lo[1024 * 256];
__device__ float g_obj[10240 * 128];
__device__ float g_sen[10240 * 128];
__device__ float g_bod[1024 * 128];
__device__ float g_xs[1024 * 688];
__device__ float g_bns_s[512], g_bns_t[512];
__device__ float g_bno_s[128], g_bno_t[128];
__device__ float g_bnb_s[256], g_bnb_t[256];
__device__ float g_bnf_s[256], g_bnf_t[256];

// ============================ helpers ============================
__device__ __forceinline__ void cp_async16(uint32_t saddr, const void* gptr) {
    asm volatile("cp.async.cg.shared.global [%0], [%1], 16;" :: "r"(saddr), "l"(gptr));
}
__device__ __forceinline__ uint32_t smem_u32(const void* p) {
    uint32_t a;
    asm("{ .reg .u64 t; cvta.to.shared.u64 t, %1; cvt.u32.u64 %0, t; }" : "=r"(a) : "l"(p));
    return a;
}
__device__ __forceinline__ void cp_commit() {
    asm volatile("cp.async.commit_group;" ::: "memory");
}
template<int N>
__device__ __forceinline__ void cp_wait() {
    asm volatile("cp.async.wait_group %0;" :: "n"(N) : "memory");
}

// ============================ BN fold prep ============================
__global__ void prep_bn_kernel(
    const float* __restrict__ gs, const float* __restrict__ bs,
    const float* __restrict__ ms, const float* __restrict__ vs,
    const float* __restrict__ go, const float* __restrict__ bo,
    const float* __restrict__ mo, const float* __restrict__ vo,
    const float* __restrict__ gb, const float* __restrict__ bb,
    const float* __restrict__ mb, const float* __restrict__ vb,
    const float* __restrict__ gf, const float* __restrict__ bfv,
    const float* __restrict__ mf, const float* __restrict__ vf,
    const float* __restrict__ bias_f)
{
    int i = threadIdx.x;
    if (i < 512) { float s = gs[i] * rsqrtf(vs[i] + BN_EPS); g_bns_s[i] = s; g_bns_t[i] = bs[i] - ms[i] * s; }
    if (i < 128) { float s = go[i] * rsqrtf(vo[i] + BN_EPS); g_bno_s[i] = s; g_bno_t[i] = bo[i] - mo[i] * s; }
    if (i < 256) { float s = gb[i] * rsqrtf(vb[i] + BN_EPS); g_bnb_s[i] = s; g_bnb_t[i] = bb[i] - mb[i] * s; }
    if (i < 256) { float s = gf[i] * rsqrtf(vf[i] + BN_EPS); g_bnf_s[i] = s; g_bnf_t[i] = (bias_f[i] - mf[i]) * s + bfv[i]; }
}

// ============================ fp32 -> bf16 hi/lo split (weights only) ============================
__global__ void split_kernel(const float4* __restrict__ src,
                             uint2* __restrict__ hi, uint2* __restrict__ lo, int n4)
{
    int i = blockIdx.x * blockDim.x + threadIdx.x;
    if (i >= n4) return;
    float4 v = src[i];
    union { __nv_bfloat16 h[4]; uint2 u; } H, L;
    H.h[0] = __float2bfloat16(v.x); L.h[0] = __float2bfloat16(v.x - __bfloat162float(H.h[0]));
    H.h[1] = __float2bfloat16(v.y); L.h[1] = __float2bfloat16(v.y - __bfloat162float(H.h[1]));
    H.h[2] = __float2bfloat16(v.z); L.h[2] = __float2bfloat16(v.z - __bfloat162float(H.h[2]));
    H.h[3] = __float2bfloat16(v.w); L.h[3] = __float2bfloat16(v.w - __bfloat162float(H.h[3]));
    hi[i] = H.u; lo[i] = L.u;
}

// ============================ fused-split bf16x3 GEMM core (GEMM1) ============================
// Single barrier per K-chunk; A planes double-buffered so the fp32->bf16 convert
// for chunk i+1 overlaps (in issue) with mma of chunk i.
// SMEM: Ahi0|Alo0|Ahi1|Alo1|Bhi0|Blo0|Bhi1|Blo1 = 8 * 18432 = 147456 B.
template<int K, bool BN_RELU>
__device__ __forceinline__ void fgemm_dev(
    int N_TOT, int bm0, int bn0,
    const float* __restrict__ A32,
    const __nv_bfloat16* __restrict__ Bhi, const __nv_bfloat16* __restrict__ Blo,
    float* __restrict__ Cf,
    __nv_bfloat16* __restrict__ Chi, __nv_bfloat16* __restrict__ Clo,
    const float* __restrict__ sc, const float* __restrict__ sh,
    char* smraw)
{
    constexpr int KITERS = K / 64;
    constexpr int LDT = 72;
    constexpr int PL = 128 * LDT * 2;     // 18432 B per plane
    const uint32_t sbase = smem_u32(smraw);

    const int tid = threadIdx.x;
    const int wid = tid >> 5;
    const int lane = tid & 31;
    const int warp_m = wid & 3;
    const int warp_n = wid >> 2;

    wmma::fragment<wmma::accumulator, 16, 16, 16, float> c[2][4];
#pragma unroll
    for (int mi = 0; mi < 2; mi++)
#pragma unroll
        for (int ni = 0; ni < 4; ni++) wmma::fill_fragment(c[mi][ni], 0.0f);

    const int lr = tid >> 3;
    const int lq = tid & 7;

    float4 areg[8];

    auto ldgA = [&](int cix) {
#pragma unroll
        for (int i = 0; i < 4; i++) {
            const float* p = A32 + (size_t)(bm0 + lr + i * 32) * K + cix * 64 + lq * 8;
            areg[i * 2]     = *reinterpret_cast<const float4*>(p);
            areg[i * 2 + 1] = *reinterpret_cast<const float4*>(p + 4);
        }
    };
    auto cpB = [&](int cix, int s) {
        const uint32_t bh = sbase + 4 * PL + s * 2 * PL;
        const uint32_t bl = bh + PL;
#pragma unroll
        for (int i = 0; i < 4; i++) {
            int r = lr + i * 32;
            cp_async16(bh + r * (LDT * 2) + lq * 16, Bhi + (size_t)(bn0 + r) * K + cix * 64 + lq * 8);
            cp_async16(bl + r * (LDT * 2) + lq * 16, Blo + (size_t)(bn0 + r) * K + cix * 64 + lq * 8);
        }
        cp_commit();
    };
    auto stsA = [&](int s) {
        char* ah = smraw + s * 2 * PL;
        char* al = ah + PL;
#pragma unroll
        for (int i = 0; i < 4; i++) {
            int r = lr + i * 32;
            float f[8] = { areg[i*2].x, areg[i*2].y, areg[i*2].z, areg[i*2].w,
                           areg[i*2+1].x, areg[i*2+1].y, areg[i*2+1].z, areg[i*2+1].w };
            union { __nv_bfloat16 h[8]; uint4 u; } H, L;
#pragma unroll
            for (int j = 0; j < 8; j++) {
                H.h[j] = __float2bfloat16(f[j]);
                L.h[j] = __float2bfloat16(f[j] - __bfloat162float(H.h[j]));
            }
            *reinterpret_cast<uint4*>(ah + r * (LDT * 2) + lq * 16) = H.u;
            *reinterpret_cast<uint4*>(al + r * (LDT * 2) + lq * 16) = L.u;
        }
    };

    // prologue: A chunk0 -> planes0, B chunk0 -> stage0, prefetch A chunk1
    ldgA(0);
    cpB(0, 0);
    stsA(0);
    if (KITERS > 1) ldgA(1);

    for (int cix = 0; cix < KITERS; ++cix) {
        const int s = cix & 1;
        cp_wait<0>();          // B(cix) resident
        __syncthreads();       // all warps: stsA(cix) done, mma(cix-1) done
        if (cix + 1 < KITERS) cpB(cix + 1, s ^ 1);   // safe: readers of B(s^1) passed barrier

        const __nv_bfloat16* ah = reinterpret_cast<const __nv_bfloat16*>(smraw + s * 2 * PL);
        const __nv_bfloat16* al = ah + PL / 2;   // PL bytes = PL/2 bf16 elems
        const __nv_bfloat16* bh = reinterpret_cast<const __nv_bfloat16*>(smraw + 4 * PL + s * 2 * PL);
        const __nv_bfloat16* bl = bh + PL / 2;
#pragma unroll
        for (int kk = 0; kk < 4; kk++) {
            wmma::fragment<wmma::matrix_a, 16, 16, 16, __nv_bfloat16, wmma::row_major> a_hi[2], a_lo[2];
            wmma::fragment<wmma::matrix_b, 16, 16, 16, __nv_bfloat16, wmma::col_major> b_hi[4], b_lo[4];
#pragma unroll
            for (int mi = 0; mi < 2; mi++) {
                wmma::load_matrix_sync(a_hi[mi], ah + (warp_m * 32 + mi * 16) * LDT + kk * 16, LDT);
                wmma::load_matrix_sync(a_lo[mi], al + (warp_m * 32 + mi * 16) * LDT + kk * 16, LDT);
            }
#pragma unroll
            for (int ni = 0; ni < 4; ni++) {
                wmma::load_matrix_sync(b_hi[ni], bh + (warp_n * 64 + ni * 16) * LDT + kk * 16, LDT);
                wmma::load_matrix_sync(b_lo[ni], bl + (warp_n * 64 + ni * 16) * LDT + kk * 16, LDT);
            }
#pragma unroll
            for (int mi = 0; mi < 2; mi++)
#pragma unroll
                for (int ni = 0; ni < 4; ni++) {
                    wmma::mma_sync(c[mi][ni], a_hi[mi], b_hi[ni], c[mi][ni]);
                    wmma::mma_sync(c[mi][ni], a_lo[mi], b_hi[ni], c[mi][ni]);
                    wmma::mma_sync(c[mi][ni], a_hi[mi], b_lo[ni], c[mi][ni]);
                }
        }
        if (cix + 1 < KITERS) {
            stsA(s ^ 1);                       // overlaps other warps' mma
            if (cix + 2 < KITERS) ldgA(cix + 2);
        }
    }
    __syncthreads();

    float* scr = reinterpret_cast<float*>(smraw) + wid * (32 * 68);
#pragma unroll
    for (int mi = 0; mi < 2; mi++)
#pragma unroll
        for (int ni = 0; ni < 4; ni++)
            wmma::store_matrix_sync(scr + mi * 16 * 68 + ni * 16, c[mi][ni], 68, wmma::mem_row_major);
    __syncwarp();

#pragma unroll
    for (int cc = 0; cc < 2; cc++) {
        const int col = bn0 + warp_n * 64 + cc * 32 + lane;
#pragma unroll
        for (int rr = 0; rr < 32; rr++) {
            const size_t row = (size_t)(bm0 + warp_m * 32 + rr);
            float v = scr[rr * 68 + cc * 32 + lane];
            if (BN_RELU) {
                v = fmaxf(fmaf(v, sc[col], sh[col]), 0.f);
                __nv_bfloat16 h = __float2bfloat16(v);
                Chi[row * N_TOT + col] = h;
                Clo[row * N_TOT + col] = __float2bfloat16(v - __bfloat162float(h));
            } else {
                Cf[row * N_TOT + col] = v;
            }
        }
    }
}

// GEMM1 mega-kernel: sen1 (320 CTAs) + obj1 (80) + body1 (16) = 416 CTAs in one launch
__global__ __launch_bounds__(256)
void gemm1_all(const float* __restrict__ sent, const float* __restrict__ feat,
               const float* __restrict__ body)
{
    extern __shared__ __align__(16) char smraw[];
    const int b = blockIdx.x;
    if (b < 320) {
        fgemm_dev<4096, true>(512, (b >> 2) * 128, (b & 3) * 128, sent,
                              g_w1s_hi, g_w1s_lo, nullptr, g_hs_hi, g_hs_lo,
                              g_bns_s, g_bns_t, smraw);
    } else if (b < 400) {
        fgemm_dev<1024, true>(128, (b - 320) * 128, 0, feat,
                              g_w1o_hi, g_w1o_lo, nullptr, g_ho_hi, g_ho_lo,
                              g_bno_s, g_bno_t, smraw);
    } else {
        const int bb = b - 400;
        fgemm_dev<2048, true>(256, (bb >> 1) * 128, (bb & 1) * 128, body,
                              g_w1b_hi, g_w1b_lo, nullptr, g_hb_hi, g_hb_lo,
                              g_bnb_s, g_bnb_t, smraw);
    }
}

// ============================ pre-split bf16x3 GEMM core (GEMM2) ============================
template<int K>
__device__ __forceinline__ void wmma_dev(
    int N_TOT, int bm0,
    const __nv_bfloat16* __restrict__ Ahi, const __nv_bfloat16* __restrict__ Alo,
    const __nv_bfloat16* __restrict__ Bhi, const __nv_bfloat16* __restrict__ Blo,
    float* __restrict__ Cf, char* smraw)
{
    constexpr int KITERS = K / 64;
    constexpr int TOTAL = 3 * KITERS;
    constexpr int LDT = 72;
    constexpr int A_STG = 128 * LDT * 2;
    constexpr int B_STG = 128 * LDT * 2;
    const uint32_t sbase = smem_u32(smraw);

    const int tid = threadIdx.x;
    const int wid = tid >> 5;
    const int lane = tid & 31;
    const int warp_m = wid & 3;
    const int warp_n = wid >> 2;

    wmma::fragment<wmma::accumulator, 16, 16, 16, float> c[2][4];
#pragma unroll
    for (int mi = 0; mi < 2; mi++)
#pragma unroll
        for (int ni = 0; ni < 4; ni++) wmma::fill_fragment(c[mi][ni], 0.0f);

    const int lr = tid >> 3;
    const int lq = tid & 7;

    auto load_stage = [&](int it, int stage) {
        const int t = it / KITERS, cix = it % KITERS;
        const __nv_bfloat16* Ap = (t == 1) ? Alo : Ahi;
        const __nv_bfloat16* Bp = (t == 2) ? Blo : Bhi;
        const uint32_t abase = sbase + stage * A_STG;
        const uint32_t bbase = sbase + 2 * A_STG + stage * B_STG;
#pragma unroll
        for (int i = 0; i < 4; i++) {
            int r = lr + i * 32;
            cp_async16(abase + r * (LDT * 2) + lq * 16,
                       Ap + (size_t)(bm0 + r) * K + cix * 64 + lq * 8);
        }
#pragma unroll
        for (int i = 0; i < 4; i++) {
            int r = lr + i * 32;
            cp_async16(bbase + r * (LDT * 2) + lq * 16,
                       Bp + (size_t)r * K + cix * 64 + lq * 8);
        }
        cp_commit();
    };

    __nv_bfloat16* As = reinterpret_cast<__nv_bfloat16*>(smraw);
    __nv_bfloat16* Bs = reinterpret_cast<__nv_bfloat16*>(smraw + 2 * A_STG);

    load_stage(0, 0);
    for (int it = 0; it < TOTAL; ++it) {
        const int stage = it & 1;
        if (it + 1 < TOTAL) {
            load_stage(it + 1, stage ^ 1);
            cp_wait<1>();
        } else {
            cp_wait<0>();
        }
        __syncthreads();

        const __nv_bfloat16* Ast = As + stage * (128 * LDT);
        const __nv_bfloat16* Bst = Bs + stage * (128 * LDT);
#pragma unroll
        for (int kk = 0; kk < 4; kk++) {
            wmma::fragment<wmma::matrix_a, 16, 16, 16, __nv_bfloat16, wmma::row_major> a[2];
            wmma::fragment<wmma::matrix_b, 16, 16, 16, __nv_bfloat16, wmma::col_major> b[4];
#pragma unroll
            for (int mi = 0; mi < 2; mi++)
                wmma::load_matrix_sync(a[mi], Ast + (warp_m * 32 + mi * 16) * LDT + kk * 16, LDT);
#pragma unroll
            for (int ni = 0; ni < 4; ni++)
                wmma::load_matrix_sync(b[ni], Bst + (warp_n * 64 + ni * 16) * LDT + kk * 16, LDT);
#pragma unroll
            for (int mi = 0; mi < 2; mi++)
#pragma unroll
                for (int ni = 0; ni < 4; ni++)
                    wmma::mma_sync(c[mi][ni], a[mi], b[ni], c[mi][ni]);
        }
        __syncthreads();
    }

    float* scr = reinterpret_cast<float*>(smraw) + wid * (32 * 68);
#pragma unroll
    for (int mi = 0; mi < 2; mi++)
#pragma unroll
        for (int ni = 0; ni < 4; ni++)
            wmma::store_matrix_sync(scr + mi * 16 * 68 + ni * 16, c[mi][ni], 68, wmma::mem_row_major);
    __syncwarp();

#pragma unroll
    for (int cc = 0; cc < 2; cc++) {
        const int col = warp_n * 64 + cc * 32 + lane;
#pragma unroll
        for (int rr = 0; rr < 32; rr++) {
            const size_t row = (size_t)(bm0 + warp_m * 32 + rr);
            Cf[row * N_TOT + col] = scr[rr * 68 + cc * 32 + lane];
        }
    }
}

// GEMM2 mega-kernel: sen2 (80) + obj2 (80) + body2 (8) = 168 CTAs
__global__ __launch_bounds__(256)
void gemm2_all()
{
    extern __shared__ __align__(16) char smraw[];
    const int b = blockIdx.x;
    if (b < 80) {
        wmma_dev<512>(128, b * 128, g_hs_hi, g_hs_lo, g_w2s_hi, g_w2s_lo, g_sen, smraw);
    } else if (b < 160) {
        wmma_dev<128>(128, (b - 80) * 128, g_ho_hi, g_ho_lo, g_w2o_hi, g_w2o_lo, g_obj, smraw);
    } else {
        wmma_dev<256>(128, (b - 160) * 128, g_hb_hi, g_hb_lo, g_w2b_hi, g_w2b_lo, g_bod, smraw);
    }
}

// ============================ fp32 SGEMM (fc, K=688) ============================
template<int BM, int BN, int BK, int TM, int TN>
__global__ void sgemm_kernel(int M, int N, int K,
    const float* __restrict__ A, const float* __restrict__ B,
    float* __restrict__ C, int ldc,
    const float* __restrict__ sc, const float* __restrict__ sh)
{
    constexpr int THREADS = (BM / TM) * (BN / TN);
    __shared__ float As[BK][BM];
    __shared__ float Bs[BK][BN];
    const int tid = threadIdx.x;
    const int bn0 = blockIdx.x * BN;
    const int bm0 = blockIdx.y * BM;
    const int tx = tid % (BN / TN);
    const int ty = tid / (BN / TN);

    float acc[TM][TN];
#pragma unroll
    for (int i = 0; i < TM; i++)
#pragma unroll
        for (int j = 0; j < TN; j++) acc[i][j] = 0.f;

    constexpr int AV = BM * BK / 4 / THREADS;
    constexpr int BV = BN * BK / 4 / THREADS;

    for (int k0 = 0; k0 < K; k0 += BK) {
#pragma unroll
        for (int i = 0; i < AV; i++) {
            int idx = tid + i * THREADS;
            int r = idx / (BK / 4), c4 = idx % (BK / 4);
            float4 v = *reinterpret_cast<const float4*>(A + (size_t)(bm0 + r) * K + k0 + c4 * 4);
            As[c4 * 4 + 0][r] = v.x; As[c4 * 4 + 1][r] = v.y;
            As[c4 * 4 + 2][r] = v.z; As[c4 * 4 + 3][r] = v.w;
        }
#pragma unroll
        for (int i = 0; i < BV; i++) {
            int idx = tid + i * THREADS;
            int r = idx / (BK / 4), c4 = idx % (BK / 4);
            float4 v = *reinterpret_cast<const float4*>(B + (size_t)(bn0 + r) * K + k0 + c4 * 4);
            Bs[c4 * 4 + 0][r] = v.x; Bs[c4 * 4 + 1][r] = v.y;
            Bs[c4 * 4 + 2][r] = v.z; Bs[c4 * 4 + 3][r] = v.w;
        }
        __syncthreads();
#pragma unroll
        for (int kk = 0; kk < BK; kk++) {
            float a[TM], b[TN];
#pragma unroll
            for (int i = 0; i < TM; i += 4) {
                float4 v = *reinterpret_cast<const float4*>(&As[kk][ty * TM + i]);
                a[i] = v.x; a[i + 1] = v.y; a[i + 2] = v.z; a[i + 3] = v.w;
            }
#pragma unroll
            for (int j = 0; j < TN; j += 4) {
                float4 v = *reinterpret_cast<const float4*>(&Bs[kk][tx * TN + j]);
                b[j] = v.x; b[j + 1] = v.y; b[j + 2] = v.z; b[j + 3] = v.w;
            }
#pragma unroll
            for (int i = 0; i < TM; i++)
#pragma unroll
                for (int j = 0; j < TN; j++)
                    acc[i][j] = fmaf(a[i], b[j], acc[i][j]);
        }
        __syncthreads();
    }
#pragma unroll
    for (int i = 0; i < TM; i++) {
        int row = bm0 + ty * TM + i;
#pragma unroll
        for (int j = 0; j < TN; j++) {
            int col = bn0 + tx * TN + j;
            float v = acc[i][j];
            if (sc) v = fmaxf(fmaf(v, sc[col], sh[col]), 0.f);
            C[(size_t)row * ldc + col] = v;
        }
    }
}

// ============================ fused attention stage ============================
__global__ void attention_kernel(
    const float* __restrict__ bbox, const float* __restrict__ word,
    const float* __restrict__ Wc1, const float* __restrict__ Wc2,
    const float* __restrict__ Wsa)
{
    __shared__ float xt[10][688];
    __shared__ float rmean[10], rmax[10], att[10];
    __shared__ float csum[688], cmax[688];

    const int b = blockIdx.x;
    const int tid = threadIdx.x;

    for (int idx = tid; idx < 10 * 688; idx += blockDim.x) {
        int n = idx / 688, f = idx % 688;
        int rn = b * 10 + n;
        float v;
        if (f < 128)       v = g_obj[rn * 128 + f];
        else if (f < 132)  v = bbox[rn * 4 + (f - 128)];
        else if (f < 432)  v = word[rn * 300 + (f - 132)];
        else if (f < 560)  v = g_sen[rn * 128 + (f - 432)];
        else               v = g_bod[b * 128 + (f - 560)];
        xt[n][f] = v;
    }
    __syncthreads();

    int w = tid / 32, lane = tid % 32;
    if (w < 10) {
        float s = 0.f, mx = -3.402823e38f;
        for (int f = lane; f < 688; f += 32) {
            float v = xt[w][f];
            s += v; mx = fmaxf(mx, v);
        }
#pragma unroll
        for (int o = 16; o; o >>= 1) {
            s += __shfl_down_sync(0xffffffff, s, o);
            mx = fmaxf(mx, __shfl_down_sync(0xffffffff, mx, o));
        }
        if (lane == 0) { rmean[w] = s * (1.f / 688.f); rmax[w] = mx; }
    }
    __syncthreads();

    if (tid == 0) {
        float h[5], o1[10], o2[10];
        for (int j = 0; j < 5; j++) {
            float s = 0.f;
            for (int i = 0; i < 10; i++) s += rmean[i] * Wc1[j * 10 + i];
            h[j] = fmaxf(s, 0.f);
        }
        for (int n = 0; n < 10; n++) {
            float s = 0.f;
            for (int j = 0; j < 5; j++) s += h[j] * Wc2[n * 5 + j];
            o1[n] = s;
        }
        for (int j = 0; j < 5; j++) {
            float s = 0.f;
            for (int i = 0; i < 10; i++) s += rmax[i] * Wc1[j * 10 + i];
            h[j] = fmaxf(s, 0.f);
        }
        for (int n = 0; n < 10; n++) {
            float s = 0.f;
            for (int j = 0; j < 5; j++) s += h[j] * Wc2[n * 5 + j];
            o2[n] = s;
        }
        for (int n = 0; n < 10; n++)
            att[n] = 1.f / (1.f + expf(-(o1[n] + o2[n])));
    }
    __syncthreads();

    for (int f = tid; f < 688; f += blockDim.x) {
        float s = 0.f, mx = -3.402823e38f;
#pragma unroll
        for (int n = 0; n < 10; n++) {
            float v = xt[n][f] * att[n];
            s += v; mx = fmaxf(mx, v);
        }
        csum[f] = s; cmax[f] = mx;
    }
    __syncthreads();

    for (int f = tid; f < 688; f += blockDim.x) {
        float sa = 0.f;
#pragma unroll
        for (int j = 0; j < 7; j++) {
            int p = f + j - 3;
            if (p >= 0 && p < 688)
                sa += Wsa[j] * (csum[p] * 0.1f) + Wsa[7 + j] * cmax[p];
        }
        float sig = 1.f / (1.f + expf(-sa));
        g_xs[b * 688 + f] = csum[f] * sig;
    }
}

// ============================ launch ============================
static inline void split(const float* src, __nv_bfloat16* hi, __nv_bfloat16* lo, size_t n) {
    int n4 = (int)(n / 4);
    split_kernel<<<(n4 + 255) / 256, 256>>>((const float4*)src, (uint2*)hi, (uint2*)lo, n4);
}

extern "C" void kernel_launch(void* const* d_in, const int* in_sizes, int n_in,
                              void* d_out, int out_size)
{
    const float* feat  = (const float*)d_in[0];
    const float* bbox  = (const float*)d_in[1];
    const float* word  = (const float*)d_in[2];
    const float* sent  = (const float*)d_in[3];
    const float* body  = (const float*)d_in[4];
    const float* W1_o  = (const float*)d_in[5];
    const float* go = (const float*)d_in[6],  *bo = (const float*)d_in[7];
    const float* mo = (const float*)d_in[8],  *vo = (const float*)d_in[9];
    const float* W2_o  = (const float*)d_in[10];
    const float* W1_s  = (const float*)d_in[11];
    const float* gs = (const float*)d_in[12], *bs = (const float*)d_in[13];
    const float* ms = (const float*)d_in[14], *vs = (const float*)d_in[15];
    const float* W2_s  = (const float*)d_in[16];
    const float* W1_b  = (const float*)d_in[17];
    const float* gb = (const float*)d_in[18], *bb = (const float*)d_in[19];
    const float* mb = (const float*)d_in[20], *vb = (const float*)d_in[21];
    const float* W2_b  = (const float*)d_in[22];
    const float* Wc1   = (const float*)d_in[23];
    const float* Wc2   = (const float*)d_in[24];
    const float* Wsa   = (const float*)d_in[25];
    const float* Wf    = (const float*)d_in[26];
    const float* bias_f= (const float*)d_in[27];
    const float* gf = (const float*)d_in[28], *bfv = (const float*)d_in[29];
    const float* mf = (const float*)d_in[30], *vf = (const float*)d_in[31];

    __nv_bfloat16 *w1s_hi, *w1s_lo, *w2s_hi, *w2s_lo, *w1o_hi, *w1o_lo, *w2o_hi, *w2o_lo;
    __nv_bfloat16 *w1b_hi, *w1b_lo, *w2b_hi, *w2b_lo;
    float *xs;
    float *bns_s, *bns_t, *bno_s, *bno_t, *bnb_s, *bnb_t, *bnf_s, *bnf_t;
#define SYM(v, s) cudaGetSymbolAddress((void**)&v, s)
    SYM(w1s_hi, g_w1s_hi); SYM(w1s_lo, g_w1s_lo); SYM(w2s_hi, g_w2s_hi); SYM(w2s_lo, g_w2s_lo);
    SYM(w1o_hi, g_w1o_hi); SYM(w1o_lo, g_w1o_lo); SYM(w2o_hi, g_w2o_hi); SYM(w2o_lo, g_w2o_lo);
    SYM(w1b_hi, g_w1b_hi); SYM(w1b_lo, g_w1b_lo); SYM(w2b_hi, g_w2b_hi); SYM(w2b_lo, g_w2b_lo);
    SYM(xs, g_xs);
    SYM(bns_s, g_bns_s); SYM(bns_t, g_bns_t); SYM(bno_s, g_bno_s); SYM(bno_t, g_bno_t);
    SYM(bnb_s, g_bnb_s); SYM(bnb_t, g_bnb_t); SYM(bnf_s, g_bnf_s); SYM(bnf_t, g_bnf_t);
#undef SYM

    const int SMF = 8 * (128 * 72 * 2);   // 147456 B: 4 A planes + 4 B planes
    const int SMB = 4 * (128 * 72 * 2);   // 73728 B
    cudaFuncSetAttribute(gemm1_all, cudaFuncAttributeMaxDynamicSharedMemorySize, SMF);
    cudaFuncSetAttribute(gemm2_all, cudaFuncAttributeMaxDynamicSharedMemorySize, SMB);

    prep_bn_kernel<<<1, 512>>>(gs, bs, ms, vs, go, bo, mo, vo,
                               gb, bb, mb, vb, gf, bfv, mf, vf, bias_f);

    // weight splits (small)
    split(W1_s, w1s_hi, w1s_lo, (size_t)512 * 4096);
    split(W2_s, w2s_hi, w2s_lo, (size_t)128 * 512);
    split(W1_o, w1o_hi, w1o_lo, (size_t)128 * 1024);
    split(W2_o, w2o_hi, w2o_lo, (size_t)128 * 128);
    split(W1_b, w1b_hi, w1b_lo, (size_t)256 * 2048);
    split(W2_b, w2b_hi, w2b_lo, (size_t)128 * 256);

    // all GEMM1s in one launch (416 CTAs), all GEMM2s in one launch (168 CTAs)
    gemm1_all<<<416, 256, SMF>>>(sent, feat, body);
    gemm2_all<<<168, 256, SMB>>>();

    attention_kernel<<<1024, 320>>>(bbox, word, Wc1, Wc2, Wsa);

    // fc: [1024,688] @ [688,256] + bias + BN + relu
    sgemm_kernel<64, 64, 16, 4, 4><<<dim3(256 / 64, 1024 / 64), 256>>>(
        1024, 256, 688, xs, Wf, (float*)d_out, 256, bnf_s, bnf_t);
}